// round 4
// baseline (speedup 1.0000x reference)
#include <cuda_runtime.h>
#include <cuda_bf16.h>
#include <cstdint>
#include <cstddef>

#define NB 1024
#define NM 14
// L = NM + 2 = 16 layers

// Ping-pong inflow buffers. Self-resetting protocol per kernel_launch call:
//   k_layer0 zeroes both; k_mid(l) reads g_inflow[l&1][b], zeroes that slot,
//   accumulates into g_inflow[(l&1)^1]. State re-established every call.
__device__ float g_inflow[2][NB];

__device__ __forceinline__ float sqrt_approx(float x) {
    float y;
    asm("sqrt.approx.f32 %0, %1;" : "=f"(y) : "f"(x));
    return y;
}
__device__ __forceinline__ void l2pf(const void* p) {
    asm volatile("prefetch.global.L2 [%0];" :: "l"(p));
}

// ---------------------------------------------------------------------------
// Register-resident bucket chain. One warp; lane holds spigots {w*32+lane}.
// Exact sequential semantics: dry spigots produce q==0 and leave H_eff
// bit-identical, so only firing spigots (lowest index first, via ballot) are
// processed serially. Firing q's recorded in registers, flushed afterwards.
// Returns warp-uniform cum.
// ---------------------------------------------------------------------------
template <bool ATOMIC>
__device__ __forceinline__ float bucket_chain(
    int lane, float H0, float inflow,
    const float2* __restrict__ S2, const float* __restrict__ T,
    float* __restrict__ nxt)
{
    const unsigned FULL = 0xFFFFFFFFu;
    const float SQ2G = 4.4271887242357310f;   // sqrt(2*9.8)

    float bh_r[32], c_r[32], q_r[32];
    // 64 independent coalesced LDG.64 + 32 LDG.32 — high MLP, L2-resident
    #pragma unroll
    for (int w = 0; w < 32; ++w) {
        float2 p = S2[w * 32 + lane];
        bh_r[w] = p.x;
        c_r[w]  = p.y;          // area (theta folded in below)
        q_r[w]  = 0.0f;
    }
    #pragma unroll
    for (int w = 0; w < 32; ++w) {
        float t = T[w * 32 + lane];
        c_r[w] = c_r[w] * t * SQ2G;
    }

    // spigot 0: uses H_eff = H0 + inflow (reference semantics)
    float bh0 = __shfl_sync(FULL, bh_r[0], 0);
    float c0  = __shfl_sync(FULL, c_r[0],  0);
    float h0  = fmaxf((H0 + inflow) - bh0, 0.0f);
    float q0  = c0 * sqrt_approx(h0);         // sqrt.approx(0) == 0
    float cum = q0;
    q_r[0] = (lane == 0) ? q0 : q_r[0];
    float H_eff = fmaf(-0.5f, cum, H0);

    #pragma unroll
    for (int w = 0; w < 32; ++w) {
        unsigned rem = (w == 0) ? 0xFFFFFFFEu : FULL;   // spigot 0 done
        while (true) {
            float h = H_eff - bh_r[w];
            float q = c_r[w] * sqrt_approx(h);          // speculative
            unsigned fire = __ballot_sync(FULL, h > 0.0f) & rem;
            if (!fire) break;
            int f = __ffs(fire) - 1;                    // lowest firing spigot
            float qf = __shfl_sync(FULL, q, f);
            cum += qf;
            H_eff = fmaf(-0.5f, cum, H0);
            q_r[w] = (lane == f) ? qf : q_r[w];
            rem &= (0xFFFFFFFEu << f);                  // lanes > f remain
        }
    }

    // flush firings (off critical path; ~10-20 actual ops per warp)
    #pragma unroll
    for (int w = 0; w < 32; ++w) {
        if (q_r[w] != 0.0f) {
            if (ATOMIC) atomicAdd(&nxt[w * 32 + lane], q_r[w]);
            else        nxt[w * 32 + lane] = q_r[w];
        }
    }
    return cum;
}

// ---------------------------------------------------------------------------
// Layer 0: block 0 (one warp) zeroes the inflow buffers and solves the head
// bucket; blocks 1..1023 prefetch mid-layer-0's 12.6 MB into L2.
// ---------------------------------------------------------------------------
__global__ void __launch_bounds__(32)
k_layer0(const float* __restrict__ H0p, const float* __restrict__ S0,
         const float* __restrict__ theta0, const float* __restrict__ precip,
         float* __restrict__ out,
         const float* __restrict__ S_mid, const float* __restrict__ theta_mid)
{
    const int lane = threadIdx.x;

    if (blockIdx.x != 0) {
        // 98304 lines total: S = 65536 x 128B, theta = 32768 x 128B
        long t0 = (long)(blockIdx.x - 1) * 96 + lane;
        #pragma unroll
        for (int k = 0; k < 3; ++k) {
            long line = t0 + k * 32;
            if (line < 65536)
                l2pf((const char*)S_mid + line * 128);
            else if (line < 98304)
                l2pf((const char*)theta_mid + (line - 65536) * 128);
        }
        return;
    }

    // zero both ping-pong buffers (same lanes later overwrite subsets)
    #pragma unroll
    for (int k = 0; k < 32; ++k) {
        g_inflow[0][k * 32 + lane] = 0.0f;
        g_inflow[1][k * 32 + lane] = 0.0f;
    }

    const float p_layer = precip[0] * (1.0f / 16.0f);
    const float H0 = H0p[0];
    float cum = bucket_chain<false>(lane, H0, p_layer,
                                    (const float2*)S0, theta0, g_inflow[0]);
    if (lane == 0) out[0] = (H0 - cum) + p_layer;
}

// ---------------------------------------------------------------------------
// Mid layer l: one warp per bucket (1024 blocks x 32 threads).
// ---------------------------------------------------------------------------
__global__ void __launch_bounds__(32)
k_mid(int l, const float* __restrict__ H_mid, const float* __restrict__ S_mid,
      const float* __restrict__ theta_mid, const float* __restrict__ precip,
      float* __restrict__ out)
{
    const int lane = threadIdx.x;
    const int b    = blockIdx.x;
    const int cur  = l & 1;
    float* __restrict__ nxt = g_inflow[cur ^ 1];

    const size_t rowoff = (size_t)l * NB + (size_t)b;
    const float2* __restrict__ S2 = (const float2*)S_mid + rowoff * NB;
    const float*  __restrict__ T  = theta_mid + rowoff * NB;

    // read my inflow and zero the slot (it becomes layer l+1's accumulator)
    float inf0 = 0.0f;
    if (lane == 0) {
        inf0 = g_inflow[cur][b];
        g_inflow[cur][b] = 0.0f;
    }
    const float p_bucket = precip[0] * (1.0f / (16.0f * 1024.0f));
    const float inflow = __shfl_sync(0xFFFFFFFFu, inf0, 0) + p_bucket;
    const float H0 = H_mid[rowoff];

    // prefetch next layer's rows for this bucket into L2 (8KB S + 4KB theta)
    if (l + 1 < NM) {
        const char* ps = (const char*)(S2 + (size_t)NB * NB);
        const char* pt = (const char*)(T  + (size_t)NB * NB);
        l2pf(ps + (size_t)lane * 128);
        l2pf(ps + (size_t)(lane + 32) * 128);
        l2pf(pt + (size_t)lane * 128);
    }

    float cum = bucket_chain<true>(lane, H0, inflow, S2, T, nxt);
    if (lane == 0) out[1 + l * NB + b] = (H0 - cum) + inflow;
}

// ---------------------------------------------------------------------------
// Last layer: 1024 buckets, one outlet spigot each (fully parallel).
// Final inflows are in g_inflow[0] (layer 13 accumulates into (13&1)^1 == 0).
// ---------------------------------------------------------------------------
__global__ void __launch_bounds__(256)
k_last(const float* __restrict__ H_last, const float* __restrict__ S_last,
       const float* __restrict__ theta_last, const float* __restrict__ precip,
       float* __restrict__ out)
{
    int j = blockIdx.x * 256 + threadIdx.x;
    if (j >= NB) return;
    const float p_bucket = precip[0] * (1.0f / (16.0f * 1024.0f));
    float inflow = g_inflow[0][j] + p_bucket;
    float H0 = H_last[j];
    float bh = S_last[2 * j + 0];
    float a  = S_last[2 * j + 1];
    float h  = fmaxf((H0 + inflow) - bh, 0.0f);
    float q  = theta_last[j] * sqrt_approx(19.6f * h) * a;
    out[1 + NM * NB + j]      = (H0 - q) + inflow;   // H_last_new
    out[1 + NM * NB + NB + j] = q;                   // q_last
}

// ---------------------------------------------------------------------------
extern "C" void kernel_launch(void* const* d_in, const int* in_sizes, int n_in,
                              void* d_out, int out_size)
{
    const float* H0         = (const float*)d_in[0];
    const float* H_mid      = (const float*)d_in[1];
    const float* H_last     = (const float*)d_in[2];
    const float* S0         = (const float*)d_in[3];
    const float* S_mid      = (const float*)d_in[4];
    const float* S_last     = (const float*)d_in[5];
    const float* theta0     = (const float*)d_in[6];
    const float* theta_mid  = (const float*)d_in[7];
    const float* theta_last = (const float*)d_in[8];
    const float* precip     = (const float*)d_in[9];
    float* out = (float*)d_out;

    k_layer0<<<1024, 32>>>(H0, S0, theta0, precip, out, S_mid, theta_mid);
    for (int l = 0; l < NM; ++l)
        k_mid<<<1024, 32>>>(l, H_mid, S_mid, theta_mid, precip, out);
    k_last<<<4, 256>>>(H_last, S_last, theta_last, precip, out);
}